// round 2
// baseline (speedup 1.0000x reference)
#include <cuda_runtime.h>
#include <cuda_bf16.h>

// OccupancyGridForestAS: 4.19M points, 8x8x8 block lookup -> 64 trees of 64^3 voxels.
//
// inputs (metadata order):
//   d_in[0]: pts            float32 [N_PTS, 3]
//   d_in[1]: occ_val_grid   float32 [64, 64, 64, 64]
//   d_in[2]: block_lookup   int32   [8, 8, 8]
// output: float32 [N_PTS]
//
// R2: 8 points/thread + streaming cache hints (__ldcs/__stcs) on the
// compulsory 64MB stream so the 64MB occ grid stays L2-resident across
// graph replays; gathers then hit L2 instead of DRAM.

#define RES   64
#define LDIM  8

__global__ void __launch_bounds__(256)
occ_forest_kernel(const float4* __restrict__ pts4,
                  const float*  __restrict__ occ,
                  const int*    __restrict__ lut,
                  float4*       __restrict__ out4,
                  int n8)
{
    int t = blockIdx.x * blockDim.x + threadIdx.x;
    if (t >= n8) return;

    // 8 points = 24 floats = 6 float4 (fully coalesced, evict-first in L2)
    float f[24];
    float4 v[6];
#pragma unroll
    for (int j = 0; j < 6; j++)
        v[j] = __ldcs(&pts4[6 * t + j]);
#pragma unroll
    for (int j = 0; j < 6; j++) {
        f[4 * j + 0] = v[j].x;
        f[4 * j + 1] = v[j].y;
        f[4 * j + 2] = v[j].z;
        f[4 * j + 3] = v[j].w;
    }

    int  idx[8];
    bool valid[8];

    // Phase 1: all index math (no memory dependencies between points)
#pragma unroll
    for (int i = 0; i < 8; i++) {
        float x = f[3 * i + 0];
        float y = f[3 * i + 1];
        float z = f[3 * i + 2];

        int bx = (int)floorf(x);
        int by = (int)floorf(y);
        int bz = (int)floorf(z);

        bool in_dom = (bx >= 0) & (bx < LDIM) &
                      (by >= 0) & (by < LDIM) &
                      (bz >= 0) & (bz < LDIM);

        int cx = min(max(bx, 0), LDIM - 1);
        int cy = min(max(by, 0), LDIM - 1);
        int cz = min(max(bz, 0), LDIM - 1);

        int bidx = __ldg(&lut[cx * (LDIM * LDIM) + cy * LDIM + cz]);
        valid[i] = in_dom && (bidx >= 0);

        // Match reference float sequence exactly:
        //   block_x = 2*(p - bcs) - 1 ; vox = clip(floor((bx*0.5+0.5)*RES), 0, RES-1)
        float bxf = 2.0f * (x - (float)cx) - 1.0f;
        float byf = 2.0f * (y - (float)cy) - 1.0f;
        float bzf = 2.0f * (z - (float)cz) - 1.0f;

        int vx = min(max((int)floorf((bxf * 0.5f + 0.5f) * (float)RES), 0), RES - 1);
        int vy = min(max((int)floorf((byf * 0.5f + 0.5f) * (float)RES), 0), RES - 1);
        int vz = min(max((int)floorf((bzf * 0.5f + 0.5f) * (float)RES), 0), RES - 1);

        idx[i] = bidx * (RES * RES * RES) + vx * (RES * RES) + vy * RES + vz;
    }

    // Phase 2: 8 independent predicated gathers (max MLP)
    float r[8];
#pragma unroll
    for (int i = 0; i < 8; i++)
        r[i] = valid[i] ? __ldg(&occ[idx[i]]) : 0.0f;

    float4 o0, o1;
    o0.x = r[0]; o0.y = r[1]; o0.z = r[2]; o0.w = r[3];
    o1.x = r[4]; o1.y = r[5]; o1.z = r[6]; o1.w = r[7];
    __stcs(&out4[2 * t + 0], o0);
    __stcs(&out4[2 * t + 1], o1);
}

extern "C" void kernel_launch(void* const* d_in, const int* in_sizes, int n_in,
                              void* d_out, int out_size)
{
    const float4* pts4 = (const float4*)d_in[0];
    const float*  occ  = (const float*)d_in[1];
    const int*    lut  = (const int*)d_in[2];
    float4*       out  = (float4*)d_out;

    int n_pts = in_sizes[0] / 3;       // 4,194,304
    int n8    = n_pts / 8;             // 524,288 (N_PTS divisible by 8)

    int threads = 256;
    int blocks  = (n8 + threads - 1) / threads;
    occ_forest_kernel<<<blocks, threads>>>(pts4, occ, lut, out, n8);
}

// round 3
// speedup vs baseline: 1.2280x; 1.2280x over previous
#include <cuda_runtime.h>
#include <cuda_bf16.h>

// OccupancyGridForestAS: 4.19M points, 8x8x8 block lookup -> 64 trees of 64^3 voxels.
//
// inputs (metadata order):
//   d_in[0]: pts            float32 [N_PTS, 3]
//   d_in[1]: occ_val_grid   float32 [64, 64, 64, 64]
//   d_in[2]: block_lookup   int32   [8, 8, 8]
// output: float32 [N_PTS]
//
// R3: 2 pts/thread (3x float2 coalesced). 8192 blocks -> 6.92 waves ->
// wave-tail overhead drops from 15.6% (R1, 3.46 waves) to 1.2%.
// Streaming hints on the 64MB compulsory stream; grid gathers via __ldg.

#define RES   64
#define LDIM  8

__global__ void __launch_bounds__(256)
occ_forest_kernel(const float2* __restrict__ pts2,
                  const float*  __restrict__ occ,
                  const int*    __restrict__ lut,
                  float2*       __restrict__ out2,
                  int n2)
{
    int t = blockIdx.x * blockDim.x + threadIdx.x;
    if (t >= n2) return;

    // 2 points = 6 floats = 3 float2 (coalesced, evict-first in L2)
    float2 v0 = __ldcs(&pts2[3 * t + 0]);
    float2 v1 = __ldcs(&pts2[3 * t + 1]);
    float2 v2 = __ldcs(&pts2[3 * t + 2]);

    float px[2] = {v0.x, v1.y};
    float py[2] = {v0.y, v2.x};
    float pz[2] = {v1.x, v2.y};

    int  idx[2];
    bool valid[2];

    // Phase 1: index math for both points (no cross-point dependencies)
#pragma unroll
    for (int i = 0; i < 2; i++) {
        float x = px[i], y = py[i], z = pz[i];

        int bx = (int)floorf(x);
        int by = (int)floorf(y);
        int bz = (int)floorf(z);

        bool in_dom = (bx >= 0) & (bx < LDIM) &
                      (by >= 0) & (by < LDIM) &
                      (bz >= 0) & (bz < LDIM);

        int cx = min(max(bx, 0), LDIM - 1);
        int cy = min(max(by, 0), LDIM - 1);
        int cz = min(max(bz, 0), LDIM - 1);

        int bidx = __ldg(&lut[cx * (LDIM * LDIM) + cy * LDIM + cz]);
        valid[i] = in_dom && (bidx >= 0);

        // Match reference float sequence exactly:
        //   block_x = 2*(p - bcs) - 1 ; vox = clip(floor((bx*0.5+0.5)*RES), 0, RES-1)
        float bxf = 2.0f * (x - (float)cx) - 1.0f;
        float byf = 2.0f * (y - (float)cy) - 1.0f;
        float bzf = 2.0f * (z - (float)cz) - 1.0f;

        int vx = min(max((int)floorf((bxf * 0.5f + 0.5f) * (float)RES), 0), RES - 1);
        int vy = min(max((int)floorf((byf * 0.5f + 0.5f) * (float)RES), 0), RES - 1);
        int vz = min(max((int)floorf((bzf * 0.5f + 0.5f) * (float)RES), 0), RES - 1);

        idx[i] = bidx * (RES * RES * RES) + vx * (RES * RES) + vy * RES + vz;
    }

    // Phase 2: 2 independent predicated gathers
    float r0 = valid[0] ? __ldg(&occ[idx[0]]) : 0.0f;
    float r1 = valid[1] ? __ldg(&occ[idx[1]]) : 0.0f;

    float2 o; o.x = r0; o.y = r1;
    __stcs(&out2[t], o);
}

extern "C" void kernel_launch(void* const* d_in, const int* in_sizes, int n_in,
                              void* d_out, int out_size)
{
    const float2* pts2 = (const float2*)d_in[0];
    const float*  occ  = (const float*)d_in[1];
    const int*    lut  = (const int*)d_in[2];
    float2*       out  = (float2*)d_out;

    int n_pts = in_sizes[0] / 3;       // 4,194,304
    int n2    = n_pts / 2;             // 2,097,152

    int threads = 256;
    int blocks  = (n2 + threads - 1) / threads;   // 8192
    occ_forest_kernel<<<blocks, threads>>>(pts2, occ, lut, out, n2);
}